// round 14
// baseline (speedup 1.0000x reference)
#include <cuda_runtime.h>
#include <cuda_fp16.h>

// WarpingLayer v14: params computed inside the gather block (warp 0 -> smem);
// pass 1 is transpose-only.
//   Pass 1: transpose x NCHW f32 -> xt NHWC f16 (float4 streaming reads).
//   Pass 2: warp 0 computes the block's 32 pixels' bilinear params (weights
//           with validity & ones-mask folded + packed corner offset) into
//           smem; then pixel-pair gather: lanes 0-15 px A / 16-31 px B, one
//           16B uint4 LDG per corner; swizzled fp16 staging (stride 67,
//           conflict-free); half2 readback + coalesced STG.32 writeback.
// Param math reproduces the JAX reference fp32 op ordering exactly.

namespace {

constexpr int B = 8;
constexpr int C = 128;
constexpr int H = 128;
constexpr int W = 256;
constexpr int HW = H * W;                     // 32768
constexpr int RS = 67;                        // staging row stride (words)

// 67 MB fp16 scratch for the transposed image (__device__ global: allowed).
__device__ __half g_xt[(size_t)B * HW * C];

// ---------------- Pass 1: NCHW f32 -> NHWC f16 transpose ----------------
__global__ __launch_bounds__(256) void transpose_kernel(const float* __restrict__ x)
{
    __shared__ float tile[32][133];
    const int hw0 = blockIdx.x * 128;
    const int c0  = blockIdx.y * 32;
    const int b   = blockIdx.z;
    const int tx  = threadIdx.x & 31;
    const int ty  = threadIdx.x >> 5;          // 0..7

    const float* px = x + (size_t)b * C * HW;
    #pragma unroll
    for (int i = 0; i < 4; ++i) {
        const int cl = ty + i * 8;             // 0..31
        const float4 v = __ldcs((const float4*)(px + (size_t)(c0 + cl) * HW + hw0) + tx);
        float* t = &tile[cl][4 * tx];
        t[0] = v.x; t[1] = v.y; t[2] = v.z; t[3] = v.w;
    }
    __syncthreads();

    __half* pt = g_xt + (size_t)b * HW * C;
    const int cpair = tx & 15;                 // channel pair 0..15
    const int hwsub = tx >> 4;                 // 0..1
    #pragma unroll
    for (int i = 0; i < 8; ++i) {
        const int hwl = (i * 8 + ty) * 2 + hwsub;          // 0..127
        const __half2 hv = __floats2half2_rn(tile[cpair * 2][hwl],
                                             tile[cpair * 2 + 1][hwl]);
        *(__half2*)(pt + (size_t)(hw0 + hwl) * C + c0 + cpair * 2) = hv;
    }
}

// ---------------- Pass 2: gather with in-block param compute ----------------
__global__ __launch_bounds__(256, 7) void warp_gather_kernel(
    const float* __restrict__ flow,
    float* __restrict__ out)
{
    __shared__ unsigned stile[32 * RS];        // 8576 B staging (half2 words)
    __shared__ float4   sw[32];                // 32 px weights
    __shared__ int      so[32];                // 32 px packed offsets

    const int tid  = threadIdx.x;
    const int warp = tid >> 5;
    const int lane = tid & 31;
    const int li   = lane & 15;
    const int hf   = lane >> 4;                // 0: pixel A, 1: pixel B

    const int pix = ((int)gridDim.x - 1 - (int)blockIdx.x) * 32;  // reversed
    const int b  = pix >> 15;
    const int h  = (pix >> 8) & (H - 1);
    const int w0 = pix & (W - 1);

    // ---- warp 0: params for the block's 32 pixels (lane = pixel) ----
    if (warp == 0) {
        const int w = w0 + lane;
        const int fbase = b * 2 * HW + h * W + w;
        const float fx = __ldg(flow + fbase);          // coalesced 128B
        const float fy = __ldg(flow + fbase + HW);     // coalesced 128B

        // Reference-exact fp32 ordering:
        const float flo_w = __fmul_rn(__fdiv_rn(__fmul_rn(fx, 2.0f), (float)(W - 1)), 1.0f);
        const float flo_h = __fmul_rn(__fdiv_rn(__fmul_rn(fy, 2.0f), (float)(H - 1)), 1.0f);
        const float step_x = __fdiv_rn(2.0f, (float)(W - 1));
        const float step_y = __fdiv_rn(2.0f, (float)(H - 1));
        const float gx = __fadd_rn(-1.0f, __fmul_rn((float)w, step_x));
        const float gy = __fadd_rn(-1.0f, __fmul_rn((float)h, step_y));

        const float ix = __fmul_rn(__fmul_rn(__fadd_rn(__fadd_rn(gx, flo_w), 1.0f), 0.5f), (float)(W - 1));
        const float iy = __fmul_rn(__fmul_rn(__fadd_rn(__fadd_rn(gy, flo_h), 1.0f), 0.5f), (float)(H - 1));

        const float x0f = floorf(ix);
        const float y0f = floorf(iy);
        const float x1f = __fadd_rn(x0f, 1.0f);
        const float y1f = __fadd_rn(y0f, 1.0f);

        const float wx1 = __fadd_rn(ix, -x0f);
        const float wx0 = __fadd_rn(1.0f, -wx1);
        const float wy1 = __fadd_rn(iy, -y0f);
        const float wy0 = __fadd_rn(1.0f, -wy1);

        const bool vx0 = (x0f >= 0.0f) && (x0f <= (float)(W - 1));
        const bool vx1 = (x1f >= 0.0f) && (x1f <= (float)(W - 1));
        const bool vy0 = (y0f >= 0.0f) && (y0f <= (float)(H - 1));
        const bool vy1 = (y1f >= 0.0f) && (y1f <= (float)(H - 1));

        float m00 = (vx0 && vy0) ? __fmul_rn(wx0, wy0) : 0.0f;
        float m01 = (vx1 && vy0) ? __fmul_rn(wx1, wy0) : 0.0f;
        float m10 = (vx0 && vy1) ? __fmul_rn(wx0, wy1) : 0.0f;
        float m11 = (vx1 && vy1) ? __fmul_rn(wx1, wy1) : 0.0f;

        const float ones_val = __fadd_rn(__fadd_rn(__fadd_rn(m00, m01), m10), m11);
        if (ones_val < 0.99999f) { m00 = m01 = m10 = m11 = 0.0f; }

        const int xi0 = min(max((int)x0f, 0), W - 1);
        const int xi1 = min(max((int)x1f, 0), W - 1);
        const int yi0 = min(max((int)y0f, 0), H - 1);
        const int yi1 = min(max((int)y1f, 0), H - 1);

        sw[lane] = make_float4(m00, m01, m10, m11);    // STS.128
        so[lane] = (yi0 * W + xi0) | ((xi1 - xi0) << 15) | ((yi1 - yi0) << 16);
    }
    __syncthreads();

    const __half* xt = g_xt + (size_t)b * HW * C;
    const int c8   = 8 * li;                           // channel base
    const int colw = 4 * li + 2 * (li >> 3);           // swizzled column word

    #pragma unroll
    for (int t = 0; t < 2; ++t) {
        const int p = warp * 4 + 2 * t + hf;           // this lane's pixel

        const float4 wv = sw[p];                       // LDS.128 (2 bcast groups)
        const int    pk = so[p];

        const int o00 = pk & 0x7FFF;
        const int dx  = (pk >> 15) & 1;
        const int o10 = o00 + ((pk >> 16) & 1) * W;
        const int o01 = o00 + dx;
        const int o11 = o10 + dx;

        // 4 independent 16B corner loads (8 channels each).
        const uint4 r00 = *(const uint4*)(xt + (size_t)o00 * C + c8);
        const uint4 r01 = *(const uint4*)(xt + (size_t)o01 * C + c8);
        const uint4 r10 = *(const uint4*)(xt + (size_t)o10 * C + c8);
        const uint4 r11 = *(const uint4*)(xt + (size_t)o11 * C + c8);

        unsigned* row = stile + RS * p + colw;
        #pragma unroll
        for (int k = 0; k < 4; ++k) {
            const unsigned u00 = (&r00.x)[k];
            const unsigned u01 = (&r01.x)[k];
            const unsigned u10 = (&r10.x)[k];
            const unsigned u11 = (&r11.x)[k];
            const float2 f00 = __half22float2(*(const __half2*)&u00);
            const float2 f01 = __half22float2(*(const __half2*)&u01);
            const float2 f10 = __half22float2(*(const __half2*)&u10);
            const float2 f11 = __half22float2(*(const __half2*)&u11);
            const float va = fmaf(f11.x, wv.w, fmaf(f10.x, wv.z, fmaf(f01.x, wv.y, f00.x * wv.x)));
            const float vb = fmaf(f11.y, wv.w, fmaf(f10.y, wv.z, fmaf(f01.y, wv.y, f00.y * wv.x)));
            const __half2 hv = __floats2half2_rn(va, vb);
            row[k] = *(const unsigned*)&hv;            // conflict-free STS.32
        }
    }

    __syncthreads();

    // Writeback: thread (warp wp, lane p) iterates channel pairs q = wp + 8j.
    // LDS word RS*p + q + 2*(q>>5): bank (3p + const)%32 -> conflict-free.
    // Two coalesced STG.32 per pair (lanes = consecutive w).
    const int p  = tid & 31;
    const int wp = tid >> 5;
    float* po = out + (size_t)b * C * HW + (size_t)h * W + w0 + p;
    #pragma unroll
    for (int j = 0; j < 8; ++j) {
        const int q = wp + 8 * j;                      // channel pair
        const unsigned u = stile[RS * p + q + 2 * (q >> 5)];
        const float2 f = __half22float2(*(const __half2*)&u);
        __stcs(po + (size_t)(2 * q) * HW,     f.x);
        __stcs(po + (size_t)(2 * q + 1) * HW, f.y);
    }
}

}  // namespace

extern "C" void kernel_launch(void* const* d_in, const int* in_sizes, int n_in,
                              void* d_out, int out_size) {
    const float* x    = (const float*)d_in[0];
    const float* flow = (const float*)d_in[1];
    float* out        = (float*)d_out;

    dim3 tgrid(HW / 128, C / 32, B);           // (256, 4, 8) transpose-only
    transpose_kernel<<<tgrid, 256>>>(x);

    const int nblocks = (B * HW) / 32;         // 8192
    warp_gather_kernel<<<nblocks, 256>>>(flow, out);
}

// round 15
// speedup vs baseline: 1.0265x; 1.0265x over previous
#include <cuda_runtime.h>
#include <cuda_fp16.h>

// WarpingLayer v14: params computed inside the gather block (warp 0 -> smem);
// pass 1 is transpose-only.
//   Pass 1: transpose x NCHW f32 -> xt NHWC f16 (float4 streaming reads).
//   Pass 2: warp 0 computes the block's 32 pixels' bilinear params (weights
//           with validity & ones-mask folded + packed corner offset) into
//           smem; then pixel-pair gather: lanes 0-15 px A / 16-31 px B, one
//           16B uint4 LDG per corner; swizzled fp16 staging (stride 67,
//           conflict-free); half2 readback + coalesced STG.32 writeback.
// Param math reproduces the JAX reference fp32 op ordering exactly.

namespace {

constexpr int B = 8;
constexpr int C = 128;
constexpr int H = 128;
constexpr int W = 256;
constexpr int HW = H * W;                     // 32768
constexpr int RS = 67;                        // staging row stride (words)

// 67 MB fp16 scratch for the transposed image (__device__ global: allowed).
__device__ __half g_xt[(size_t)B * HW * C];

// ---------------- Pass 1: NCHW f32 -> NHWC f16 transpose ----------------
__global__ __launch_bounds__(256) void transpose_kernel(const float* __restrict__ x)
{
    __shared__ float tile[32][133];
    const int hw0 = blockIdx.x * 128;
    const int c0  = blockIdx.y * 32;
    const int b   = blockIdx.z;
    const int tx  = threadIdx.x & 31;
    const int ty  = threadIdx.x >> 5;          // 0..7

    const float* px = x + (size_t)b * C * HW;
    #pragma unroll
    for (int i = 0; i < 4; ++i) {
        const int cl = ty + i * 8;             // 0..31
        const float4 v = __ldcs((const float4*)(px + (size_t)(c0 + cl) * HW + hw0) + tx);
        float* t = &tile[cl][4 * tx];
        t[0] = v.x; t[1] = v.y; t[2] = v.z; t[3] = v.w;
    }
    __syncthreads();

    __half* pt = g_xt + (size_t)b * HW * C;
    const int cpair = tx & 15;                 // channel pair 0..15
    const int hwsub = tx >> 4;                 // 0..1
    #pragma unroll
    for (int i = 0; i < 8; ++i) {
        const int hwl = (i * 8 + ty) * 2 + hwsub;          // 0..127
        const __half2 hv = __floats2half2_rn(tile[cpair * 2][hwl],
                                             tile[cpair * 2 + 1][hwl]);
        *(__half2*)(pt + (size_t)(hw0 + hwl) * C + c0 + cpair * 2) = hv;
    }
}

// ---------------- Pass 2: gather with in-block param compute ----------------
__global__ __launch_bounds__(256, 7) void warp_gather_kernel(
    const float* __restrict__ flow,
    float* __restrict__ out)
{
    __shared__ unsigned stile[32 * RS];        // 8576 B staging (half2 words)
    __shared__ float4   sw[32];                // 32 px weights
    __shared__ int      so[32];                // 32 px packed offsets

    const int tid  = threadIdx.x;
    const int warp = tid >> 5;
    const int lane = tid & 31;
    const int li   = lane & 15;
    const int hf   = lane >> 4;                // 0: pixel A, 1: pixel B

    const int pix = ((int)gridDim.x - 1 - (int)blockIdx.x) * 32;  // reversed
    const int b  = pix >> 15;
    const int h  = (pix >> 8) & (H - 1);
    const int w0 = pix & (W - 1);

    // ---- warp 0: params for the block's 32 pixels (lane = pixel) ----
    if (warp == 0) {
        const int w = w0 + lane;
        const int fbase = b * 2 * HW + h * W + w;
        const float fx = __ldg(flow + fbase);          // coalesced 128B
        const float fy = __ldg(flow + fbase + HW);     // coalesced 128B

        // Reference-exact fp32 ordering:
        const float flo_w = __fmul_rn(__fdiv_rn(__fmul_rn(fx, 2.0f), (float)(W - 1)), 1.0f);
        const float flo_h = __fmul_rn(__fdiv_rn(__fmul_rn(fy, 2.0f), (float)(H - 1)), 1.0f);
        const float step_x = __fdiv_rn(2.0f, (float)(W - 1));
        const float step_y = __fdiv_rn(2.0f, (float)(H - 1));
        const float gx = __fadd_rn(-1.0f, __fmul_rn((float)w, step_x));
        const float gy = __fadd_rn(-1.0f, __fmul_rn((float)h, step_y));

        const float ix = __fmul_rn(__fmul_rn(__fadd_rn(__fadd_rn(gx, flo_w), 1.0f), 0.5f), (float)(W - 1));
        const float iy = __fmul_rn(__fmul_rn(__fadd_rn(__fadd_rn(gy, flo_h), 1.0f), 0.5f), (float)(H - 1));

        const float x0f = floorf(ix);
        const float y0f = floorf(iy);
        const float x1f = __fadd_rn(x0f, 1.0f);
        const float y1f = __fadd_rn(y0f, 1.0f);

        const float wx1 = __fadd_rn(ix, -x0f);
        const float wx0 = __fadd_rn(1.0f, -wx1);
        const float wy1 = __fadd_rn(iy, -y0f);
        const float wy0 = __fadd_rn(1.0f, -wy1);

        const bool vx0 = (x0f >= 0.0f) && (x0f <= (float)(W - 1));
        const bool vx1 = (x1f >= 0.0f) && (x1f <= (float)(W - 1));
        const bool vy0 = (y0f >= 0.0f) && (y0f <= (float)(H - 1));
        const bool vy1 = (y1f >= 0.0f) && (y1f <= (float)(H - 1));

        float m00 = (vx0 && vy0) ? __fmul_rn(wx0, wy0) : 0.0f;
        float m01 = (vx1 && vy0) ? __fmul_rn(wx1, wy0) : 0.0f;
        float m10 = (vx0 && vy1) ? __fmul_rn(wx0, wy1) : 0.0f;
        float m11 = (vx1 && vy1) ? __fmul_rn(wx1, wy1) : 0.0f;

        const float ones_val = __fadd_rn(__fadd_rn(__fadd_rn(m00, m01), m10), m11);
        if (ones_val < 0.99999f) { m00 = m01 = m10 = m11 = 0.0f; }

        const int xi0 = min(max((int)x0f, 0), W - 1);
        const int xi1 = min(max((int)x1f, 0), W - 1);
        const int yi0 = min(max((int)y0f, 0), H - 1);
        const int yi1 = min(max((int)y1f, 0), H - 1);

        sw[lane] = make_float4(m00, m01, m10, m11);    // STS.128
        so[lane] = (yi0 * W + xi0) | ((xi1 - xi0) << 15) | ((yi1 - yi0) << 16);
    }
    __syncthreads();

    const __half* xt = g_xt + (size_t)b * HW * C;
    const int c8   = 8 * li;                           // channel base
    const int colw = 4 * li + 2 * (li >> 3);           // swizzled column word

    #pragma unroll
    for (int t = 0; t < 2; ++t) {
        const int p = warp * 4 + 2 * t + hf;           // this lane's pixel

        const float4 wv = sw[p];                       // LDS.128 (2 bcast groups)
        const int    pk = so[p];

        const int o00 = pk & 0x7FFF;
        const int dx  = (pk >> 15) & 1;
        const int o10 = o00 + ((pk >> 16) & 1) * W;
        const int o01 = o00 + dx;
        const int o11 = o10 + dx;

        // 4 independent 16B corner loads (8 channels each).
        const uint4 r00 = *(const uint4*)(xt + (size_t)o00 * C + c8);
        const uint4 r01 = *(const uint4*)(xt + (size_t)o01 * C + c8);
        const uint4 r10 = *(const uint4*)(xt + (size_t)o10 * C + c8);
        const uint4 r11 = *(const uint4*)(xt + (size_t)o11 * C + c8);

        unsigned* row = stile + RS * p + colw;
        #pragma unroll
        for (int k = 0; k < 4; ++k) {
            const unsigned u00 = (&r00.x)[k];
            const unsigned u01 = (&r01.x)[k];
            const unsigned u10 = (&r10.x)[k];
            const unsigned u11 = (&r11.x)[k];
            const float2 f00 = __half22float2(*(const __half2*)&u00);
            const float2 f01 = __half22float2(*(const __half2*)&u01);
            const float2 f10 = __half22float2(*(const __half2*)&u10);
            const float2 f11 = __half22float2(*(const __half2*)&u11);
            const float va = fmaf(f11.x, wv.w, fmaf(f10.x, wv.z, fmaf(f01.x, wv.y, f00.x * wv.x)));
            const float vb = fmaf(f11.y, wv.w, fmaf(f10.y, wv.z, fmaf(f01.y, wv.y, f00.y * wv.x)));
            const __half2 hv = __floats2half2_rn(va, vb);
            row[k] = *(const unsigned*)&hv;            // conflict-free STS.32
        }
    }

    __syncthreads();

    // Writeback: thread (warp wp, lane p) iterates channel pairs q = wp + 8j.
    // LDS word RS*p + q + 2*(q>>5): bank (3p + const)%32 -> conflict-free.
    // Two coalesced STG.32 per pair (lanes = consecutive w).
    const int p  = tid & 31;
    const int wp = tid >> 5;
    float* po = out + (size_t)b * C * HW + (size_t)h * W + w0 + p;
    #pragma unroll
    for (int j = 0; j < 8; ++j) {
        const int q = wp + 8 * j;                      // channel pair
        const unsigned u = stile[RS * p + q + 2 * (q >> 5)];
        const float2 f = __half22float2(*(const __half2*)&u);
        __stcs(po + (size_t)(2 * q) * HW,     f.x);
        __stcs(po + (size_t)(2 * q + 1) * HW, f.y);
    }
}

}  // namespace

extern "C" void kernel_launch(void* const* d_in, const int* in_sizes, int n_in,
                              void* d_out, int out_size) {
    const float* x    = (const float*)d_in[0];
    const float* flow = (const float*)d_in[1];
    float* out        = (float*)d_out;

    dim3 tgrid(HW / 128, C / 32, B);           // (256, 4, 8) transpose-only
    transpose_kernel<<<tgrid, 256>>>(x);

    const int nblocks = (B * HW) / 32;         // 8192
    warp_gather_kernel<<<nblocks, 256>>>(flow, out);
}